// round 6
// baseline (speedup 1.0000x reference)
#include <cuda_runtime.h>
#include <cuda_bf16.h>
#include <math.h>
#include <cstdint>
#include <cstddef>

typedef __nv_bfloat16 bf16;

#define MROWS 32768
#define HD    512
#define RSTRIDE 1024            // interleaved row stride in bf16 elems (hi+lo)
#define WELEMS  ((size_t)HD * RSTRIDE)

#define BM 128
#define BN 64
#define NTH 256

// smem: 1024 B header (bias) + 2 stages x 48 KB
//   stage: A = 2 parities x 128 rows x 128 B = 32 KB, W = 2 x 64 x 128 B = 16 KB
#define A_OFF  0u
#define W_OFF  32768u
#define STAGE  49152u
#define SMEMB  (1024u + 2u*STAGE)   // 99328

// ------------- scratch (static device arrays, no runtime alloc) -------------
__device__ bf16 g_Xhl [(size_t)MROWS * RSTRIDE];
__device__ bf16 g_H0hl[(size_t)MROWS * RSTRIDE];
__device__ bf16 g_H1hl[(size_t)MROWS * RSTRIDE];
__device__ bf16 g_Yhl [(size_t)MROWS * RSTRIDE];
__device__ bf16 g_Whl [8 * WELEMS];

// ----------------------------- PTX helpers ----------------------------------
__device__ __forceinline__ uint32_t s2u(const void* p) {
    uint32_t a;
    asm("{ .reg .u64 t; cvta.to.shared.u64 t, %1; cvt.u32.u64 %0, t; }" : "=r"(a) : "l"(p));
    return a;
}
__device__ __forceinline__ void cp16(uint32_t dst, const void* src) {
    asm volatile("cp.async.cg.shared.global [%0], [%1], 16;" :: "r"(dst), "l"(src));
}
#define CP_COMMIT() asm volatile("cp.async.commit_group;" ::: "memory")

__device__ __forceinline__ void ldsm4(uint32_t& r0, uint32_t& r1, uint32_t& r2,
                                      uint32_t& r3, uint32_t addr) {
    asm volatile("ldmatrix.sync.aligned.m8n8.x4.shared.b16 {%0,%1,%2,%3}, [%4];"
                 : "=r"(r0), "=r"(r1), "=r"(r2), "=r"(r3) : "r"(addr));
}
__device__ __forceinline__ void mma16816(float* c, const uint32_t* a, const uint32_t* b) {
    asm volatile(
        "mma.sync.aligned.m16n8k16.row.col.f32.bf16.bf16.f32 "
        "{%0,%1,%2,%3}, {%4,%5,%6,%7}, {%8,%9}, {%0,%1,%2,%3};"
        : "+f"(c[0]), "+f"(c[1]), "+f"(c[2]), "+f"(c[3])
        : "r"(a[0]), "r"(a[1]), "r"(a[2]), "r"(a[3]), "r"(b[0]), "r"(b[1]));
}

// fast accurate tanh: 1 - 2/(exp(2x)+1)
__device__ __forceinline__ float tfast(float x) {
    float e, r;
    asm("ex2.approx.f32 %0, %1;" : "=f"(e) : "f"(x * 2.8853900817779268f));
    asm("rcp.approx.f32 %0, %1;" : "=f"(r) : "f"(e + 1.0f));
    return fmaf(-2.0f, r, 1.0f);
}

__device__ __forceinline__ void split2(float x, bf16& h, bf16& l) {
    h = __float2bfloat16_rn(x);
    l = __float2bfloat16_rn(x - __bfloat162float(h));
}

// ---------------------------- GEMM stage kernel -----------------------------
// acc[m][n] = sum_k A0[m][k]*W0[n][k] (+A1*W1 if DUAL) + bias, opt tanh.
// Interleaved hi/lo layout: row = 16 chunks of [32 hi bf16 | 32 lo bf16].
// Computes Ah*Wh + Ah*Wl + Al*Wh with fp32 accumulation.
template<bool DUAL, bool DO_TANH, bool HSF, bool TRANS>
__global__ void __launch_bounds__(NTH, 2) gemm_stage(
    const bf16* __restrict__ A0, const bf16* __restrict__ W0,
    const bf16* __restrict__ A1, const bf16* __restrict__ W1,
    const float* __restrict__ bias0, const float* __restrict__ bias1,
    bf16* __restrict__ outHL, float* __restrict__ outF, float* __restrict__ hsf)
{
    extern __shared__ char smem[];
    const uint32_t sb = s2u(smem);
    const int t   = threadIdx.x;
    const int wid = t >> 5;
    const int lid = t & 31;
    const int n0  = blockIdx.x * BN;
    const int m0  = blockIdx.y * BM;
    const int wm  = wid & 3;       // 0..3 (M, 32 rows)
    const int wn  = wid >> 2;      // 0..1 (N, 32 cols)

    if (t < BN) {
        float b = bias0[n0 + t];
        if (bias1) b += bias1[n0 + t];
        ((float*)smem)[t] = b;
    }

    float acc[2][4][4];
#pragma unroll
    for (int mt = 0; mt < 2; ++mt)
#pragma unroll
        for (int nt = 0; nt < 4; ++nt)
#pragma unroll
            for (int e = 0; e < 4; ++e) acc[mt][nt][e] = 0.0f;

    // ldmatrix per-lane addressing (scheme verified R4/R5)
    const int q   = lid >> 3;
    const int lr8 = lid & 7;
    const int sws = lr8;
    const uint32_t aOff = (uint32_t)((wm * 32 + (q & 1) * 8 + lr8) * 128);
    const int aHalf = q >> 1;
    const uint32_t bOff = (uint32_t)((wn * 32 + (q >> 1) * 8 + lr8) * 128);
    const int bHalf = q & 1;

    const int NC = DUAL ? 16 : 8;    // KC=64 chunks

    auto load_chunk = [&](int cc) {
        const bf16* A = (DUAL && cc >= 8) ? A1 : A0;
        const bf16* W = (DUAL && cc >= 8) ? W1 : W0;
        const int kb = (cc & 7) * 2;             // base kc32 index
        const uint32_t st = sb + 1024 + (uint32_t)(cc & 1) * STAGE;
#pragma unroll
        for (int i = 0; i < 8; ++i) {            // A: 2 par x 128 rows x 8 c16
            int idx = t + i * NTH;
            int p = idx >> 10, rem = idx & 1023;
            int r = rem >> 3, c = rem & 7;
            uint32_t d = st + A_OFF + (uint32_t)p * 16384u
                       + r * 128 + (uint32_t)((c ^ (r & 7)) << 4);
            cp16(d, A + (size_t)(m0 + r) * RSTRIDE + (kb + p) * 64 + c * 8);
        }
#pragma unroll
        for (int i = 0; i < 4; ++i) {            // W: 2 par x 64 rows x 8 c16
            int idx = t + i * NTH;
            int p = idx >> 9, rem = idx & 511;
            int r = rem >> 3, c = rem & 7;
            uint32_t d = st + W_OFF + (uint32_t)p * 8192u
                       + r * 128 + (uint32_t)((c ^ (r & 7)) << 4);
            cp16(d, W + (size_t)(n0 + r) * RSTRIDE + (kb + p) * 64 + c * 8);
        }
        CP_COMMIT();
    };

    load_chunk(0);

#pragma unroll 1
    for (int cc = 0; cc < NC; ++cc) {
        asm volatile("cp.async.wait_group 0;" ::: "memory");
        __syncthreads();
        if (cc + 1 < NC) load_chunk(cc + 1);

        const uint32_t st = sb + 1024 + (uint32_t)(cc & 1) * STAGE;

#pragma unroll
        for (int p = 0; p < 2; ++p) {
            const uint32_t aB = st + A_OFF + (uint32_t)p * 16384u + aOff;
            const uint32_t bB = st + W_OFF + (uint32_t)p * 8192u + bOff;
#pragma unroll
            for (int ks = 0; ks < 2; ++ks) {
                const uint32_t caH = (uint32_t)(((2 * ks + aHalf) ^ sws) << 4);
                const uint32_t caL = (uint32_t)(((4 + 2 * ks + aHalf) ^ sws) << 4);
                const uint32_t cbH = (uint32_t)(((2 * ks + bHalf) ^ sws) << 4);
                const uint32_t cbL = (uint32_t)(((4 + 2 * ks + bHalf) ^ sws) << 4);
                uint32_t a[2][4], b[4][2];

                // A_hi
#pragma unroll
                for (int mt = 0; mt < 2; ++mt)
                    ldsm4(a[mt][0], a[mt][1], a[mt][2], a[mt][3],
                          aB + mt * 2048 + caH);
                // W_lo -> acc += Ah*Wl
#pragma unroll
                for (int bt = 0; bt < 2; ++bt)
                    ldsm4(b[2*bt][0], b[2*bt][1], b[2*bt+1][0], b[2*bt+1][1],
                          bB + bt * 2048 + cbL);
#pragma unroll
                for (int mt = 0; mt < 2; ++mt)
#pragma unroll
                    for (int nt = 0; nt < 4; ++nt)
                        mma16816(acc[mt][nt], a[mt], b[nt]);
                // W_hi -> acc += Ah*Wh
#pragma unroll
                for (int bt = 0; bt < 2; ++bt)
                    ldsm4(b[2*bt][0], b[2*bt][1], b[2*bt+1][0], b[2*bt+1][1],
                          bB + bt * 2048 + cbH);
#pragma unroll
                for (int mt = 0; mt < 2; ++mt)
#pragma unroll
                    for (int nt = 0; nt < 4; ++nt)
                        mma16816(acc[mt][nt], a[mt], b[nt]);
                // A_lo -> acc += Al*Wh
#pragma unroll
                for (int mt = 0; mt < 2; ++mt)
                    ldsm4(a[mt][0], a[mt][1], a[mt][2], a[mt][3],
                          aB + mt * 2048 + caL);
#pragma unroll
                for (int mt = 0; mt < 2; ++mt)
#pragma unroll
                    for (int nt = 0; nt < 4; ++nt)
                        mma16816(acc[mt][nt], a[mt], b[nt]);
            }
        }
    }

    // ------------------------------ epilogue --------------------------------
    const float* bsm = (const float*)smem;
    const int lq = lid >> 2;
    const int lr = lid & 3;

#pragma unroll
    for (int mt = 0; mt < 2; ++mt) {
#pragma unroll
        for (int hf = 0; hf < 2; ++hf) {
            const int m = m0 + wm * 32 + mt * 16 + lq + hf * 8;
#pragma unroll
            for (int nt = 0; nt < 4; ++nt) {
                const int n = n0 + wn * 32 + nt * 8 + lr * 2;
                float x0 = acc[mt][nt][hf * 2 + 0] + bsm[n - n0];
                float x1 = acc[mt][nt][hf * 2 + 1] + bsm[n - n0 + 1];
                if (DO_TANH) { x0 = tfast(x0); x1 = tfast(x1); }

                if (TRANS) {
                    const int s = m & 4095, bb = m >> 12;
                    float* dst = outF + ((size_t)(s * 8 + bb)) * HD + n;
                    *(float2*)dst = make_float2(x0, x1);
                } else {
                    __nv_bfloat162 hh, ll;
                    split2(x0, hh.x, ll.x);
                    split2(x1, hh.y, ll.y);
                    bf16* base = outHL + (size_t)m * RSTRIDE + (n >> 5) * 64;
                    const int w = n & 31;
                    *(__nv_bfloat162*)(base + w)      = hh;
                    *(__nv_bfloat162*)(base + 32 + w) = ll;
                }
                if (HSF && ((m & 4095) == 4095)) {
                    float* hd = hsf + (size_t)(m >> 12) * HD + n;
                    *(float2*)hd = make_float2(x0, x1);
                }
            }
        }
    }
}

// ------------------------------- prep kernels -------------------------------
__global__ void k_split_x(const float* __restrict__ x, bf16* __restrict__ dst)
{
    const size_t idx = (size_t)blockIdx.x * blockDim.x + threadIdx.x;
    const size_t row = idx >> 4;
    const int    kc  = (int)(idx & 15);
    const float* src = x + row * 512 + kc * 32;
    bf16* d = dst + row * RSTRIDE + kc * 64;

    uint32_t hi[16], lo[16];
#pragma unroll
    for (int j = 0; j < 8; ++j) {
        float4 v = *(const float4*)(src + j * 4);
        __nv_bfloat162 h0, l0, h1, l1;
        split2(v.x, h0.x, l0.x); split2(v.y, h0.y, l0.y);
        split2(v.z, h1.x, l1.x); split2(v.w, h1.y, l1.y);
        hi[2*j]   = *(uint32_t*)&h0; hi[2*j+1] = *(uint32_t*)&h1;
        lo[2*j]   = *(uint32_t*)&l0; lo[2*j+1] = *(uint32_t*)&l1;
    }
#pragma unroll
    for (int j = 0; j < 4; ++j) {
        ((uint4*)d)[j]      = *(uint4*)(hi + 4*j);
        ((uint4*)(d+32))[j] = *(uint4*)(lo + 4*j);
    }
}

struct WPtrs { const float* p[8]; };

__global__ void k_split_w(WPtrs wp, bf16* __restrict__ dst)
{
    const size_t idx = (size_t)blockIdx.x * blockDim.x + threadIdx.x;
    const int slot = (int)(idx >> 13);
    const size_t row = (idx >> 4) & 511;
    const int    kc  = (int)(idx & 15);
    const float* src = wp.p[slot] + row * 512 + kc * 32;
    bf16* d = dst + (size_t)slot * WELEMS + row * RSTRIDE + kc * 64;

    uint32_t hi[16], lo[16];
#pragma unroll
    for (int j = 0; j < 8; ++j) {
        float4 v = *(const float4*)(src + j * 4);
        __nv_bfloat162 h0, l0, h1, l1;
        split2(v.x, h0.x, l0.x); split2(v.y, h0.y, l0.y);
        split2(v.z, h1.x, l1.x); split2(v.w, h1.y, l1.y);
        hi[2*j]   = *(uint32_t*)&h0; hi[2*j+1] = *(uint32_t*)&h1;
        lo[2*j]   = *(uint32_t*)&l0; lo[2*j+1] = *(uint32_t*)&l1;
    }
#pragma unroll
    for (int j = 0; j < 4; ++j) {
        ((uint4*)d)[j]      = *(uint4*)(hi + 4*j);
        ((uint4*)(d+32))[j] = *(uint4*)(lo + 4*j);
    }
}

// --------------------------------- launcher ---------------------------------
extern "C" void kernel_launch(void* const* d_in, const int* in_sizes, int n_in,
                              void* d_out, int out_size)
{
    const float* xs     = (const float*)d_in[0];
    const float* W_xh0  = (const float*)d_in[1];
    const float* b_xh0  = (const float*)d_in[2];
    const float* b_hh0  = (const float*)d_in[4];
    const float* W_hy0  = (const float*)d_in[5];
    const float* b_hy0  = (const float*)d_in[6];
    const float* W_xh_h = (const float*)d_in[7];
    const float* b_xh_h = (const float*)d_in[8];
    const float* W_hh_h = (const float*)d_in[9];
    const float* b_hh_h = (const float*)d_in[10];
    const float* W_hy_h = (const float*)d_in[11];
    const float* b_hy_h = (const float*)d_in[12];

    float* out = (float*)d_out;
    float* hs_final = out + (size_t)4096 * 8 * HD;

    bf16 *Xhl, *H0hl, *H1hl, *Yhl, *Whl;
    cudaGetSymbolAddress((void**)&Xhl,  g_Xhl);
    cudaGetSymbolAddress((void**)&H0hl, g_H0hl);
    cudaGetSymbolAddress((void**)&H1hl, g_H1hl);
    cudaGetSymbolAddress((void**)&Yhl,  g_Yhl);
    cudaGetSymbolAddress((void**)&Whl,  g_Whl);

    cudaFuncSetAttribute(gemm_stage<false, true,  false, false>,
                         cudaFuncAttributeMaxDynamicSharedMemorySize, SMEMB);
    cudaFuncSetAttribute(gemm_stage<false, false, false, false>,
                         cudaFuncAttributeMaxDynamicSharedMemorySize, SMEMB);
    cudaFuncSetAttribute(gemm_stage<true,  true,  false, false>,
                         cudaFuncAttributeMaxDynamicSharedMemorySize, SMEMB);
    cudaFuncSetAttribute(gemm_stage<true,  true,  true,  false>,
                         cudaFuncAttributeMaxDynamicSharedMemorySize, SMEMB);
    cudaFuncSetAttribute(gemm_stage<false, false, false, true >,
                         cudaFuncAttributeMaxDynamicSharedMemorySize, SMEMB);

    // prep: hi/lo interleaved splits
    k_split_x<<<2048, 256>>>(xs, Xhl);
    WPtrs wp;
    wp.p[0] = W_xh0;            wp.p[1] = W_hy0;
    wp.p[2] = W_hh_h;           wp.p[3] = W_xh_h;
    wp.p[4] = W_hy_h;           wp.p[5] = W_hh_h + 512*512;
    wp.p[6] = W_xh_h + 512*512; wp.p[7] = W_hy_h + 512*512;
    k_split_w<<<256, 256>>>(wp, Whl);

    dim3 grid(HD / BN, MROWS / BM);   // (8, 256) = 2048 CTAs
    dim3 block(NTH);
#define WS(s) (Whl + (size_t)(s) * WELEMS)

    // 1) h0 = tanh(X @ W_xh0^T + b_xh0 + b_hh0)
    gemm_stage<false, true, false, false><<<grid, block, SMEMB>>>(
        Xhl, WS(0), nullptr, nullptr, b_xh0, b_hh0, H0hl, nullptr, nullptr);
    // 2) y0 = h0 @ W_hy0^T + b_hy0
    gemm_stage<false, false, false, false><<<grid, block, SMEMB>>>(
        H0hl, WS(1), nullptr, nullptr, b_hy0, nullptr, Yhl, nullptr, nullptr);
    // 3) h1 = tanh(h0 @ W_hh_h[0]^T + y0 @ W_xh_h[0]^T + biases)
    gemm_stage<true, true, false, false><<<grid, block, SMEMB>>>(
        H0hl, WS(2), Yhl, WS(3), b_hh_h, b_xh_h, H1hl, nullptr, nullptr);
    // 4) y1 = h1 @ W_hy_h[0]^T + b_hy_h[0]
    gemm_stage<false, false, false, false><<<grid, block, SMEMB>>>(
        H1hl, WS(4), nullptr, nullptr, b_hy_h, nullptr, Yhl, nullptr, nullptr);
    // 5) h2 = tanh(h1 @ W_hh_h[1]^T + y1 @ W_xh_h[1]^T + biases) + hs_final
    gemm_stage<true, true, true, false><<<grid, block, SMEMB>>>(
        H1hl, WS(5), Yhl, WS(6), b_hh_h + HD, b_xh_h + HD, H0hl, nullptr, hs_final);
    // 6) outputs = (h2 @ W_hy_h[1]^T + b_hy_h[1]) -> [S, B, H] fp32
    gemm_stage<false, false, false, true><<<grid, block, SMEMB>>>(
        H0hl, WS(7), nullptr, nullptr, b_hy_h + HD, nullptr, nullptr, out, nullptr);
#undef WS
}

// round 7
// speedup vs baseline: 1.3601x; 1.3601x over previous
#include <cuda_runtime.h>
#include <cuda_bf16.h>
#include <math.h>
#include <cstdint>
#include <cstddef>

typedef __nv_bfloat16 bf16;

#define MROWS 32768
#define HD    512
#define WSZ   (512*512)
#define RSTRIDE 1024            // interleaved row stride in bf16 elems (hi+lo)
#define WELEMS  ((size_t)HD * RSTRIDE)

#define BM 128
#define BN 128
#define NTH 256

// smem: 1024 B header (bias) + 3 stages x 32 KB (A 16K + W 16K)
#define A_OFF  0u
#define W_OFF  16384u
#define STAGE  32768u
#define NSTAGE 3
#define SMEMB  (1024u + NSTAGE*STAGE)   // 99328

// ------------- scratch (static device arrays, no runtime alloc) -------------
__device__ bf16  g_Xhl [(size_t)MROWS * RSTRIDE];
__device__ bf16  g_H0hl[(size_t)MROWS * RSTRIDE];
__device__ bf16  g_H1hl[(size_t)MROWS * RSTRIDE];
__device__ bf16  g_Whl [4 * WELEMS];
__device__ float g_Weff[2 * WSZ];
__device__ float g_beff[2 * HD];

// ----------------------------- PTX helpers ----------------------------------
__device__ __forceinline__ uint32_t s2u(const void* p) {
    uint32_t a;
    asm("{ .reg .u64 t; cvta.to.shared.u64 t, %1; cvt.u32.u64 %0, t; }" : "=r"(a) : "l"(p));
    return a;
}
__device__ __forceinline__ void cp16(uint32_t dst, const void* src) {
    asm volatile("cp.async.cg.shared.global [%0], [%1], 16;" :: "r"(dst), "l"(src));
}
#define CP_COMMIT() asm volatile("cp.async.commit_group;" ::: "memory")

__device__ __forceinline__ void ldsm4(uint32_t& r0, uint32_t& r1, uint32_t& r2,
                                      uint32_t& r3, uint32_t addr) {
    asm volatile("ldmatrix.sync.aligned.m8n8.x4.shared.b16 {%0,%1,%2,%3}, [%4];"
                 : "=r"(r0), "=r"(r1), "=r"(r2), "=r"(r3) : "r"(addr));
}
__device__ __forceinline__ void mma16816(float* c, const uint32_t* a, const uint32_t* b) {
    asm volatile(
        "mma.sync.aligned.m16n8k16.row.col.f32.bf16.bf16.f32 "
        "{%0,%1,%2,%3}, {%4,%5,%6,%7}, {%8,%9}, {%0,%1,%2,%3};"
        : "+f"(c[0]), "+f"(c[1]), "+f"(c[2]), "+f"(c[3])
        : "r"(a[0]), "r"(a[1]), "r"(a[2]), "r"(a[3]), "r"(b[0]), "r"(b[1]));
}

// fast accurate tanh: 1 - 2/(exp(2x)+1)
__device__ __forceinline__ float tfast(float x) {
    float e, r;
    asm("ex2.approx.f32 %0, %1;" : "=f"(e) : "f"(x * 2.8853900817779268f));
    asm("rcp.approx.f32 %0, %1;" : "=f"(r) : "f"(e + 1.0f));
    return fmaf(-2.0f, r, 1.0f);
}

__device__ __forceinline__ void split2(float x, bf16& h, bf16& l) {
    h = __float2bfloat16_rn(x);
    l = __float2bfloat16_rn(x - __bfloat162float(h));
}

// ---------------------------- GEMM stage kernel -----------------------------
// acc[m][n] = sum_k A[m][k]*W[n][k] + bias, opt tanh.
// Interleaved hi/lo layout: row = 16 chunks of [32 hi bf16 | 32 lo bf16].
// Computes Ah*Wh + Ah*Wl + Al*Wh with fp32 accumulation.
template<bool DO_TANH, bool HSF, bool TRANS>
__global__ void __launch_bounds__(NTH, 2) gemm_stage(
    const bf16* __restrict__ A0, const bf16* __restrict__ W0,
    const float* __restrict__ bias0, const float* __restrict__ bias1,
    bf16* __restrict__ outHL, float* __restrict__ outF, float* __restrict__ hsf)
{
    extern __shared__ char smem[];
    const uint32_t sb = s2u(smem);
    const int t   = threadIdx.x;
    const int wid = t >> 5;
    const int lid = t & 31;
    const int n0  = blockIdx.x * BN;
    const int m0  = blockIdx.y * BM;
    const int wm  = wid & 3;       // 0..3 (M, 32 rows)
    const int wn  = wid >> 2;      // 0..1 (N, 64 cols)

    if (t < BN) {
        float b = bias0[n0 + t];
        if (bias1) b += bias1[n0 + t];
        ((float*)smem)[t] = b;
    }

    float acc[2][8][4];
#pragma unroll
    for (int mt = 0; mt < 2; ++mt)
#pragma unroll
        for (int nt = 0; nt < 8; ++nt)
#pragma unroll
            for (int e = 0; e < 4; ++e) acc[mt][nt][e] = 0.0f;

    // ldmatrix per-lane addressing (scheme verified R4/R5)
    const int q   = lid >> 3;
    const int lr8 = lid & 7;
    const int sws = lr8;
    const uint32_t aOff = (uint32_t)((wm * 32 + (q & 1) * 8 + lr8) * 128);
    const int aHalf = q >> 1;
    const uint32_t bOff = (uint32_t)((wn * 64 + (q >> 1) * 8 + lr8) * 128);
    const int bHalf = q & 1;

    const int NC = 16;   // KC=32 chunks over K=512

    auto load_chunk = [&](int cc) {
        const int kc = cc;
        const uint32_t st = sb + 1024 + (uint32_t)(cc % NSTAGE) * STAGE;
#pragma unroll
        for (int i = 0; i < 4; ++i) {                 // A: 128 rows x 8 c16
            int idx = t + i * NTH;
            int r = idx >> 3, c = idx & 7;
            uint32_t d = st + A_OFF + r * 128 + (uint32_t)((c ^ (r & 7)) << 4);
            cp16(d, A0 + (size_t)(m0 + r) * RSTRIDE + kc * 64 + c * 8);
        }
#pragma unroll
        for (int i = 0; i < 4; ++i) {                 // W: 128 rows x 8 c16
            int idx = t + i * NTH;
            int r = idx >> 3, c = idx & 7;
            uint32_t d = st + W_OFF + r * 128 + (uint32_t)((c ^ (r & 7)) << 4);
            cp16(d, W0 + (size_t)(n0 + r) * RSTRIDE + kc * 64 + c * 8);
        }
        CP_COMMIT();
    };

    load_chunk(0);
    load_chunk(1);

#pragma unroll 1
    for (int cc = 0; cc < NC; ++cc) {
        if (cc < NC - 1) asm volatile("cp.async.wait_group 1;" ::: "memory");
        else             asm volatile("cp.async.wait_group 0;" ::: "memory");
        __syncthreads();
        if (cc + 2 < NC) load_chunk(cc + 2);

        const uint32_t st = sb + 1024 + (uint32_t)(cc % NSTAGE) * STAGE;
        const uint32_t aB = st + A_OFF + aOff;
        const uint32_t bB = st + W_OFF + bOff;

#pragma unroll
        for (int ks = 0; ks < 2; ++ks) {
            // chunk columns: hi = 0..3, lo = 4..7 within the 128 B row
            const uint32_t caH = (uint32_t)(((2 * ks + aHalf) ^ sws) << 4);
            const uint32_t caL = (uint32_t)(((4 + 2 * ks + aHalf) ^ sws) << 4);
            const uint32_t cbH = (uint32_t)(((2 * ks + bHalf) ^ sws) << 4);
            const uint32_t cbL = (uint32_t)(((4 + 2 * ks + bHalf) ^ sws) << 4);
            uint32_t a[2][4], b[8][2];

            // A_hi
#pragma unroll
            for (int mt = 0; mt < 2; ++mt)
                ldsm4(a[mt][0], a[mt][1], a[mt][2], a[mt][3],
                      aB + mt * 2048 + caH);
            // W_lo -> acc += Ah*Wl
#pragma unroll
            for (int bt = 0; bt < 4; ++bt)
                ldsm4(b[2*bt][0], b[2*bt][1], b[2*bt+1][0], b[2*bt+1][1],
                      bB + bt * 2048 + cbL);
#pragma unroll
            for (int mt = 0; mt < 2; ++mt)
#pragma unroll
                for (int nt = 0; nt < 8; ++nt)
                    mma16816(acc[mt][nt], a[mt], b[nt]);
            // W_hi -> acc += Ah*Wh
#pragma unroll
            for (int bt = 0; bt < 4; ++bt)
                ldsm4(b[2*bt][0], b[2*bt][1], b[2*bt+1][0], b[2*bt+1][1],
                      bB + bt * 2048 + cbH);
#pragma unroll
            for (int mt = 0; mt < 2; ++mt)
#pragma unroll
                for (int nt = 0; nt < 8; ++nt)
                    mma16816(acc[mt][nt], a[mt], b[nt]);
            // A_lo -> acc += Al*Wh
#pragma unroll
            for (int mt = 0; mt < 2; ++mt)
                ldsm4(a[mt][0], a[mt][1], a[mt][2], a[mt][3],
                      aB + mt * 2048 + caL);
#pragma unroll
            for (int mt = 0; mt < 2; ++mt)
#pragma unroll
                for (int nt = 0; nt < 8; ++nt)
                    mma16816(acc[mt][nt], a[mt], b[nt]);
        }
    }

    // ------------------------------ epilogue --------------------------------
    const float* bsm = (const float*)smem;
    const int lq = lid >> 2;
    const int lr = lid & 3;

#pragma unroll
    for (int mt = 0; mt < 2; ++mt) {
#pragma unroll
        for (int hf = 0; hf < 2; ++hf) {
            const int m = m0 + wm * 32 + mt * 16 + lq + hf * 8;
#pragma unroll
            for (int nt = 0; nt < 8; ++nt) {
                const int n = n0 + wn * 64 + nt * 8 + lr * 2;
                float x0 = acc[mt][nt][hf * 2 + 0] + bsm[n - n0];
                float x1 = acc[mt][nt][hf * 2 + 1] + bsm[n - n0 + 1];
                if (DO_TANH) { x0 = tfast(x0); x1 = tfast(x1); }

                if (TRANS) {
                    const int s = m & 4095, bb = m >> 12;
                    float* dst = outF + ((size_t)(s * 8 + bb)) * HD + n;
                    *(float2*)dst = make_float2(x0, x1);
                } else {
                    __nv_bfloat162 hh, ll;
                    split2(x0, hh.x, ll.x);
                    split2(x1, hh.y, ll.y);
                    bf16* base = outHL + (size_t)m * RSTRIDE + (n >> 5) * 64;
                    const int w = n & 31;
                    *(__nv_bfloat162*)(base + w)      = hh;
                    *(__nv_bfloat162*)(base + 32 + w) = ll;
                }
                if (HSF && ((m & 4095) == 4095)) {
                    float* hd = hsf + (size_t)(m >> 12) * HD + n;
                    *(float2*)hd = make_float2(x0, x1);
                }
            }
        }
    }
}

// ------------------------------- prep kernels -------------------------------
// Weff = Whh + Wxh @ Why  (fp32, 512x512 per layer). 64x64 tiles, 256 threads.
struct WeffP {
    const float* A[2];     // Wxh  [n][k]
    const float* B[2];     // Why  [k][j]
    const float* Wadd[2];  // Whh  [n][j]
    float*       C[2];     // Weff [n][j]
};

__global__ void __launch_bounds__(256) k_weff(WeffP wp)
{
    const int l = blockIdx.z;
    const float* __restrict__ A = wp.A[l];
    const float* __restrict__ B = wp.B[l];
    const float* __restrict__ Wadd = wp.Wadd[l];
    float* __restrict__ C = wp.C[l];

    __shared__ float As[16][64];
    __shared__ float Bs[16][64];
    const int t  = threadIdx.x;
    const int tx = t & 15, ty = t >> 4;
    const int m0 = blockIdx.y * 64, n0 = blockIdx.x * 64;

    float acc[4][4] = {};
#pragma unroll 1
    for (int kt = 0; kt < 512; kt += 16) {
#pragma unroll
        for (int e = t; e < 1024; e += 256) {
            int am = e >> 4, ak = e & 15;
            As[ak][am] = A[(size_t)(m0 + am) * 512 + kt + ak];
            int bj = e & 63, bk = e >> 6;
            Bs[bk][bj] = B[(size_t)(kt + bk) * 512 + n0 + bj];
        }
        __syncthreads();
#pragma unroll
        for (int k = 0; k < 16; ++k) {
            float af[4], bf[4];
#pragma unroll
            for (int i = 0; i < 4; ++i) af[i] = As[k][ty * 4 + i];
#pragma unroll
            for (int j = 0; j < 4; ++j) bf[j] = Bs[k][tx * 4 + j];
#pragma unroll
            for (int i = 0; i < 4; ++i)
#pragma unroll
                for (int j = 0; j < 4; ++j)
                    acc[i][j] = fmaf(af[i], bf[j], acc[i][j]);
        }
        __syncthreads();
    }
#pragma unroll
    for (int i = 0; i < 4; ++i)
#pragma unroll
        for (int j = 0; j < 4; ++j) {
            size_t idx = (size_t)(m0 + ty * 4 + i) * 512 + n0 + tx * 4 + j;
            C[idx] = Wadd[idx] + acc[i][j];
        }
}

// beff = bhh + bxh + Wxh @ bhy   (per layer)
struct BeffP {
    const float* Wxh[2];
    const float* bhh[2];
    const float* bxh[2];
    const float* bhy[2];
    float*       out[2];
};

__global__ void k_beff(BeffP bp)
{
    const int l = blockIdx.x;
    const int n = threadIdx.x;
    const float* W = bp.Wxh[l] + (size_t)n * 512;
    const float* bh = bp.bhy[l];
    float s = 0.0f;
#pragma unroll 4
    for (int k = 0; k < 512; ++k) s = fmaf(W[k], bh[k], s);
    bp.out[l][n] = bp.bhh[l][n] + bp.bxh[l][n] + s;
}

// hi/lo interleaved splits
__global__ void k_split_x(const float* __restrict__ x, bf16* __restrict__ dst)
{
    const size_t idx = (size_t)blockIdx.x * blockDim.x + threadIdx.x;
    const size_t row = idx >> 4;
    const int    kc  = (int)(idx & 15);
    const float* src = x + row * 512 + kc * 32;
    bf16* d = dst + row * RSTRIDE + kc * 64;

    uint32_t hi[16], lo[16];
#pragma unroll
    for (int j = 0; j < 8; ++j) {
        float4 v = *(const float4*)(src + j * 4);
        __nv_bfloat162 h0, l0, h1, l1;
        split2(v.x, h0.x, l0.x); split2(v.y, h0.y, l0.y);
        split2(v.z, h1.x, l1.x); split2(v.w, h1.y, l1.y);
        hi[2*j]   = *(uint32_t*)&h0; hi[2*j+1] = *(uint32_t*)&h1;
        lo[2*j]   = *(uint32_t*)&l0; lo[2*j+1] = *(uint32_t*)&l1;
    }
#pragma unroll
    for (int j = 0; j < 4; ++j) {
        ((uint4*)d)[j]      = *(uint4*)(hi + 4*j);
        ((uint4*)(d+32))[j] = *(uint4*)(lo + 4*j);
    }
}

struct WPtrs { const float* p[4]; };

__global__ void k_split_w(WPtrs wp, bf16* __restrict__ dst)
{
    const size_t idx = (size_t)blockIdx.x * blockDim.x + threadIdx.x;
    const int slot = (int)(idx >> 13);
    const size_t row = (idx >> 4) & 511;
    const int    kc  = (int)(idx & 15);
    const float* src = wp.p[slot] + row * 512 + kc * 32;
    bf16* d = dst + (size_t)slot * WELEMS + row * RSTRIDE + kc * 64;

    uint32_t hi[16], lo[16];
#pragma unroll
    for (int j = 0; j < 8; ++j) {
        float4 v = *(const float4*)(src + j * 4);
        __nv_bfloat162 h0, l0, h1, l1;
        split2(v.x, h0.x, l0.x); split2(v.y, h0.y, l0.y);
        split2(v.z, h1.x, l1.x); split2(v.w, h1.y, l1.y);
        hi[2*j]   = *(uint32_t*)&h0; hi[2*j+1] = *(uint32_t*)&h1;
        lo[2*j]   = *(uint32_t*)&l0; lo[2*j+1] = *(uint32_t*)&l1;
    }
#pragma unroll
    for (int j = 0; j < 4; ++j) {
        ((uint4*)d)[j]      = *(uint4*)(hi + 4*j);
        ((uint4*)(d+32))[j] = *(uint4*)(lo + 4*j);
    }
}

// --------------------------------- launcher ---------------------------------
extern "C" void kernel_launch(void* const* d_in, const int* in_sizes, int n_in,
                              void* d_out, int out_size)
{
    const float* xs     = (const float*)d_in[0];
    const float* W_xh0  = (const float*)d_in[1];
    const float* b_xh0  = (const float*)d_in[2];
    const float* b_hh0  = (const float*)d_in[4];
    const float* W_hy0  = (const float*)d_in[5];
    const float* b_hy0  = (const float*)d_in[6];
    const float* W_xh_h = (const float*)d_in[7];
    const float* b_xh_h = (const float*)d_in[8];
    const float* W_hh_h = (const float*)d_in[9];
    const float* b_hh_h = (const float*)d_in[10];
    const float* W_hy_h = (const float*)d_in[11];
    const float* b_hy_h = (const float*)d_in[12];

    float* out = (float*)d_out;
    float* hs_final = out + (size_t)4096 * 8 * HD;

    bf16 *Xhl, *H0hl, *H1hl, *Whl;
    float *Weff, *beff;
    cudaGetSymbolAddress((void**)&Xhl,  g_Xhl);
    cudaGetSymbolAddress((void**)&H0hl, g_H0hl);
    cudaGetSymbolAddress((void**)&H1hl, g_H1hl);
    cudaGetSymbolAddress((void**)&Whl,  g_Whl);
    cudaGetSymbolAddress((void**)&Weff, g_Weff);
    cudaGetSymbolAddress((void**)&beff, g_beff);

    cudaFuncSetAttribute(gemm_stage<true,  false, false>,
                         cudaFuncAttributeMaxDynamicSharedMemorySize, SMEMB);
    cudaFuncSetAttribute(gemm_stage<true,  true,  false>,
                         cudaFuncAttributeMaxDynamicSharedMemorySize, SMEMB);
    cudaFuncSetAttribute(gemm_stage<false, false, true >,
                         cudaFuncAttributeMaxDynamicSharedMemorySize, SMEMB);

    // ---- prep: fused effective weights/biases ----
    WeffP wep;
    wep.A[0] = W_xh_h;        wep.A[1] = W_xh_h + WSZ;
    wep.B[0] = W_hy0;         wep.B[1] = W_hy_h;
    wep.Wadd[0] = W_hh_h;     wep.Wadd[1] = W_hh_h + WSZ;
    wep.C[0] = Weff;          wep.C[1] = Weff + WSZ;
    k_weff<<<dim3(8, 8, 2), 256>>>(wep);

    BeffP bep;
    bep.Wxh[0] = W_xh_h;      bep.Wxh[1] = W_xh_h + WSZ;
    bep.bhh[0] = b_hh_h;      bep.bhh[1] = b_hh_h + HD;
    bep.bxh[0] = b_xh_h;      bep.bxh[1] = b_xh_h + HD;
    bep.bhy[0] = b_hy0;       bep.bhy[1] = b_hy_h;
    bep.out[0] = beff;        bep.out[1] = beff + HD;
    k_beff<<<2, 512>>>(bep);

    // ---- prep: hi/lo interleaved splits ----
    k_split_x<<<2048, 256>>>(xs, Xhl);
    WPtrs wp;
    wp.p[0] = W_xh0;
    wp.p[1] = Weff;           // fused layer-0 weight (device scratch, fp32)
    wp.p[2] = Weff + WSZ;     // fused layer-1 weight
    wp.p[3] = W_hy_h + WSZ;   // final output projection
    k_split_w<<<128, 256>>>(wp, Whl);

    dim3 grid(HD / BN, MROWS / BM);   // (4, 256) = 1024 CTAs
    dim3 block(NTH);
#define WS(s) (Whl + (size_t)(s) * WELEMS)

    // 1) h0 = tanh(X @ W_xh0^T + b_xh0 + b_hh0)
    gemm_stage<true, false, false><<<grid, block, SMEMB>>>(
        Xhl, WS(0), b_xh0, b_hh0, H0hl, nullptr, nullptr);
    // 2) h1 = tanh(h0 @ Weff0^T + beff0)
    gemm_stage<true, false, false><<<grid, block, SMEMB>>>(
        H0hl, WS(1), beff, nullptr, H1hl, nullptr, nullptr);
    // 3) h2 = tanh(h1 @ Weff1^T + beff1)  (+ hs_final)
    gemm_stage<true, true, false><<<grid, block, SMEMB>>>(
        H1hl, WS(2), beff + HD, nullptr, H0hl, nullptr, hs_final);
    // 4) outputs = (h2 @ W_hy_h[1]^T + b_hy_h[1]) -> [S, B, H] fp32
    gemm_stage<false, false, true><<<grid, block, SMEMB>>>(
        H0hl, WS(3), b_hy_h + HD, nullptr, nullptr, out, nullptr);
#undef WS
}

// round 8
// speedup vs baseline: 1.6438x; 1.2086x over previous
#include <cuda_runtime.h>
#include <cuda_bf16.h>
#include <math.h>
#include <cstdint>
#include <cstddef>

typedef __nv_bfloat16 bf16;

#define MROWS 32768
#define HD    512
#define WSZ   (512*512)
#define RSTRIDE 1024            // interleaved row stride in bf16 elems (hi+lo)
#define WELEMS  ((size_t)HD * RSTRIDE)

#define BM 128
#define BN 128
#define NTH 256

// smem: 1024 B header (bias) + 3 stages x 32 KB (A 16K + W 16K)
#define A_OFF  0u
#define W_OFF  16384u
#define STAGE  32768u
#define NSTAGE 3
#define SMEMB  (1024u + NSTAGE*STAGE)   // 99328

// ------------- scratch (static device arrays, no runtime alloc) -------------
__device__ bf16  g_Xhl [(size_t)MROWS * RSTRIDE];
__device__ bf16  g_H0hl[(size_t)MROWS * RSTRIDE];
__device__ bf16  g_H1hl[(size_t)MROWS * RSTRIDE];
__device__ bf16  g_Whl [4 * WELEMS];
__device__ float g_beff[2 * HD];

// ----------------------------- PTX helpers ----------------------------------
__device__ __forceinline__ uint32_t s2u(const void* p) {
    uint32_t a;
    asm("{ .reg .u64 t; cvta.to.shared.u64 t, %1; cvt.u32.u64 %0, t; }" : "=r"(a) : "l"(p));
    return a;
}
__device__ __forceinline__ void cp16(uint32_t dst, const void* src) {
    asm volatile("cp.async.cg.shared.global [%0], [%1], 16;" :: "r"(dst), "l"(src));
}
#define CP_COMMIT() asm volatile("cp.async.commit_group;" ::: "memory")

__device__ __forceinline__ void ldsm4(uint32_t& r0, uint32_t& r1, uint32_t& r2,
                                      uint32_t& r3, uint32_t addr) {
    asm volatile("ldmatrix.sync.aligned.m8n8.x4.shared.b16 {%0,%1,%2,%3}, [%4];"
                 : "=r"(r0), "=r"(r1), "=r"(r2), "=r"(r3) : "r"(addr));
}
__device__ __forceinline__ void mma16816(float* c, const uint32_t* a, const uint32_t* b) {
    asm volatile(
        "mma.sync.aligned.m16n8k16.row.col.f32.bf16.bf16.f32 "
        "{%0,%1,%2,%3}, {%4,%5,%6,%7}, {%8,%9}, {%0,%1,%2,%3};"
        : "+f"(c[0]), "+f"(c[1]), "+f"(c[2]), "+f"(c[3])
        : "r"(a[0]), "r"(a[1]), "r"(a[2]), "r"(a[3]), "r"(b[0]), "r"(b[1]));
}

// fast accurate tanh: 1 - 2/(exp(2x)+1)
__device__ __forceinline__ float tfast(float x) {
    float e, r;
    asm("ex2.approx.f32 %0, %1;" : "=f"(e) : "f"(x * 2.8853900817779268f));
    asm("rcp.approx.f32 %0, %1;" : "=f"(r) : "f"(e + 1.0f));
    return fmaf(-2.0f, r, 1.0f);
}

__device__ __forceinline__ void split2(float x, bf16& h, bf16& l) {
    h = __float2bfloat16_rn(x);
    l = __float2bfloat16_rn(x - __bfloat162float(h));
}

// ---------------------------- GEMM stage kernel -----------------------------
// acc[m][n] = sum_k A[m][k]*W[n][k] + bias, opt tanh.
// Interleaved hi/lo layout: row = 16 chunks of [32 hi bf16 | 32 lo bf16].
// Computes Ah*Wh + Ah*Wl + Al*Wh with fp32 accumulation.
template<bool DO_TANH, bool HSF, bool TRANS>
__global__ void __launch_bounds__(NTH, 2) gemm_stage(
    const bf16* __restrict__ A0, const bf16* __restrict__ W0,
    const float* __restrict__ bias0, const float* __restrict__ bias1,
    bf16* __restrict__ outHL, float* __restrict__ outF, float* __restrict__ hsf)
{
    extern __shared__ char smem[];
    const uint32_t sb = s2u(smem);
    const int t   = threadIdx.x;
    const int wid = t >> 5;
    const int lid = t & 31;
    const int n0  = blockIdx.x * BN;
    const int m0  = blockIdx.y * BM;
    const int wm  = wid & 3;       // 0..3 (M, 32 rows)
    const int wn  = wid >> 2;      // 0..1 (N, 64 cols)

    if (t < BN) {
        float b = bias0[n0 + t];
        if (bias1) b += bias1[n0 + t];
        ((float*)smem)[t] = b;
    }

    float acc[2][8][4];
#pragma unroll
    for (int mt = 0; mt < 2; ++mt)
#pragma unroll
        for (int nt = 0; nt < 8; ++nt)
#pragma unroll
            for (int e = 0; e < 4; ++e) acc[mt][nt][e] = 0.0f;

    const int q   = lid >> 3;
    const int lr8 = lid & 7;
    const int sws = lr8;
    const uint32_t aOff = (uint32_t)((wm * 32 + (q & 1) * 8 + lr8) * 128);
    const int aHalf = q >> 1;
    const uint32_t bOff = (uint32_t)((wn * 64 + (q >> 1) * 8 + lr8) * 128);
    const int bHalf = q & 1;

    const int NC = 16;   // KC=32 chunks over K=512

    auto load_chunk = [&](int cc) {
        const int kc = cc;
        const uint32_t st = sb + 1024 + (uint32_t)(cc % NSTAGE) * STAGE;
#pragma unroll
        for (int i = 0; i < 4; ++i) {                 // A: 128 rows x 8 c16
            int idx = t + i * NTH;
            int r = idx >> 3, c = idx & 7;
            uint32_t d = st + A_OFF + r * 128 + (uint32_t)((c ^ (r & 7)) << 4);
            cp16(d, A0 + (size_t)(m0 + r) * RSTRIDE + kc * 64 + c * 8);
        }
#pragma unroll
        for (int i = 0; i < 4; ++i) {                 // W: 128 rows x 8 c16
            int idx = t + i * NTH;
            int r = idx >> 3, c = idx & 7;
            uint32_t d = st + W_OFF + r * 128 + (uint32_t)((c ^ (r & 7)) << 4);
            cp16(d, W0 + (size_t)(n0 + r) * RSTRIDE + kc * 64 + c * 8);
        }
        CP_COMMIT();
    };

    load_chunk(0);
    load_chunk(1);

#pragma unroll 1
    for (int cc = 0; cc < NC; ++cc) {
        if (cc < NC - 1) asm volatile("cp.async.wait_group 1;" ::: "memory");
        else             asm volatile("cp.async.wait_group 0;" ::: "memory");
        __syncthreads();
        if (cc + 2 < NC) load_chunk(cc + 2);

        const uint32_t st = sb + 1024 + (uint32_t)(cc % NSTAGE) * STAGE;
        const uint32_t aB = st + A_OFF + aOff;
        const uint32_t bB = st + W_OFF + bOff;

#pragma unroll
        for (int ks = 0; ks < 2; ++ks) {
            const uint32_t caH = (uint32_t)(((2 * ks + aHalf) ^ sws) << 4);
            const uint32_t caL = (uint32_t)(((4 + 2 * ks + aHalf) ^ sws) << 4);
            const uint32_t cbH = (uint32_t)(((2 * ks + bHalf) ^ sws) << 4);
            const uint32_t cbL = (uint32_t)(((4 + 2 * ks + bHalf) ^ sws) << 4);
            uint32_t a[2][4], b[8][2];

            // A_hi
#pragma unroll
            for (int mt = 0; mt < 2; ++mt)
                ldsm4(a[mt][0], a[mt][1], a[mt][2], a[mt][3],
                      aB + mt * 2048 + caH);
            // W_lo -> acc += Ah*Wl
#pragma unroll
            for (int bt = 0; bt < 4; ++bt)
                ldsm4(b[2*bt][0], b[2*bt][1], b[2*bt+1][0], b[2*bt+1][1],
                      bB + bt * 2048 + cbL);
#pragma unroll
            for (int mt = 0; mt < 2; ++mt)
#pragma unroll
                for (int nt = 0; nt < 8; ++nt)
                    mma16816(acc[mt][nt], a[mt], b[nt]);
            // W_hi -> acc += Ah*Wh
#pragma unroll
            for (int bt = 0; bt < 4; ++bt)
                ldsm4(b[2*bt][0], b[2*bt][1], b[2*bt+1][0], b[2*bt+1][1],
                      bB + bt * 2048 + cbH);
#pragma unroll
            for (int mt = 0; mt < 2; ++mt)
#pragma unroll
                for (int nt = 0; nt < 8; ++nt)
                    mma16816(acc[mt][nt], a[mt], b[nt]);
            // A_lo -> acc += Al*Wh
#pragma unroll
            for (int mt = 0; mt < 2; ++mt)
                ldsm4(a[mt][0], a[mt][1], a[mt][2], a[mt][3],
                      aB + mt * 2048 + caL);
#pragma unroll
            for (int mt = 0; mt < 2; ++mt)
#pragma unroll
                for (int nt = 0; nt < 8; ++nt)
                    mma16816(acc[mt][nt], a[mt], b[nt]);
        }
    }

    // ------------------------------ epilogue --------------------------------
    const float* bsm = (const float*)smem;
    const int lq = lid >> 2;
    const int lr = lid & 3;

#pragma unroll
    for (int mt = 0; mt < 2; ++mt) {
#pragma unroll
        for (int hf = 0; hf < 2; ++hf) {
            const int m = m0 + wm * 32 + mt * 16 + lq + hf * 8;
#pragma unroll
            for (int nt = 0; nt < 8; ++nt) {
                const int n = n0 + wn * 64 + nt * 8 + lr * 2;
                float x0 = acc[mt][nt][hf * 2 + 0] + bsm[n - n0];
                float x1 = acc[mt][nt][hf * 2 + 1] + bsm[n - n0 + 1];
                if (DO_TANH) { x0 = tfast(x0); x1 = tfast(x1); }

                if (TRANS) {
                    const int s = m & 4095, bb = m >> 12;
                    float* dst = outF + ((size_t)(s * 8 + bb)) * HD + n;
                    *(float2*)dst = make_float2(x0, x1);
                } else {
                    __nv_bfloat162 hh, ll;
                    split2(x0, hh.x, ll.x);
                    split2(x1, hh.y, ll.y);
                    bf16* base = outHL + (size_t)m * RSTRIDE + (n >> 5) * 64;
                    const int w = n & 31;
                    *(__nv_bfloat162*)(base + w)      = hh;
                    *(__nv_bfloat162*)(base + 32 + w) = ll;
                }
                if (HSF && ((m & 4095) == 4095)) {
                    float* hd = hsf + (size_t)(m >> 12) * HD + n;
                    *(float2*)hd = make_float2(x0, x1);
                }
            }
        }
    }
}

// ------------------------------- prep kernels -------------------------------
// Weff = Whh + Wxh @ Why, written DIRECTLY in hi/lo-interleaved bf16 layout.
struct WeffP {
    const float* A[2];     // Wxh  [n][j]
    const float* B[2];     // Why  [j][k]
    const float* Wadd[2];  // Whh  [n][k]
    bf16*        C[2];     // interleaved dst (g_Whl slot)
};

__global__ void __launch_bounds__(256) k_weff(WeffP wp)
{
    const int l = blockIdx.z;
    const float* __restrict__ A = wp.A[l];
    const float* __restrict__ B = wp.B[l];
    const float* __restrict__ Wadd = wp.Wadd[l];
    bf16* __restrict__ C = wp.C[l];

    __shared__ float As[16][64];
    __shared__ float Bs[16][64];
    const int t  = threadIdx.x;
    const int tx = t & 15, ty = t >> 4;
    const int m0 = blockIdx.y * 64, n0 = blockIdx.x * 64;

    float acc[4][4] = {};
#pragma unroll 1
    for (int kt = 0; kt < 512; kt += 16) {
#pragma unroll
        for (int e = t; e < 1024; e += 256) {
            int am = e >> 4, ak = e & 15;
            As[ak][am] = A[(size_t)(m0 + am) * 512 + kt + ak];
            int bj = e & 63, bk = e >> 6;
            Bs[bk][bj] = B[(size_t)(kt + bk) * 512 + n0 + bj];
        }
        __syncthreads();
#pragma unroll
        for (int k = 0; k < 16; ++k) {
            float af[4], bf[4];
#pragma unroll
            for (int i = 0; i < 4; ++i) af[i] = As[k][ty * 4 + i];
#pragma unroll
            for (int j = 0; j < 4; ++j) bf[j] = Bs[k][tx * 4 + j];
#pragma unroll
            for (int i = 0; i < 4; ++i)
#pragma unroll
                for (int j = 0; j < 4; ++j)
                    acc[i][j] = fmaf(af[i], bf[j], acc[i][j]);
        }
        __syncthreads();
    }

    // epilogue: write hi/lo interleaved rows (row = n, reduction dim = k)
    const int kcol = n0 + tx * 4;               // 4 consecutive k per thread
#pragma unroll
    for (int i = 0; i < 4; ++i) {
        const int n = m0 + ty * 4 + i;
        bf16 h[4], lo[4];
#pragma unroll
        for (int j = 0; j < 4; ++j) {
            float v = Wadd[(size_t)n * 512 + kcol + j] + acc[i][j];
            split2(v, h[j], lo[j]);
        }
        bf16* base = C + (size_t)n * RSTRIDE + (kcol >> 5) * 64 + (kcol & 31);
        *(uint2*)base        = *(uint2*)h;
        *(uint2*)(base + 32) = *(uint2*)lo;
    }
}

// beff = bhh + bxh + Wxh @ bhy : one warp per output element
struct BeffP {
    const float* Wxh[2];
    const float* bhh[2];
    const float* bxh[2];
    const float* bhy[2];
    float*       out[2];
};

__global__ void k_beff(BeffP bp)
{
    const int gw = (blockIdx.x * blockDim.x + threadIdx.x) >> 5;
    const int l = gw >> 9;
    const int n = gw & 511;
    const int lane = threadIdx.x & 31;
    const float* W  = bp.Wxh[l] + (size_t)n * 512 + lane * 16;
    const float* bh = bp.bhy[l] + lane * 16;
    float s = 0.0f;
#pragma unroll
    for (int k = 0; k < 16; k += 4) {
        float4 w = *(const float4*)(W + k);
        float4 b = *(const float4*)(bh + k);
        s = fmaf(w.x, b.x, s); s = fmaf(w.y, b.y, s);
        s = fmaf(w.z, b.z, s); s = fmaf(w.w, b.w, s);
    }
#pragma unroll
    for (int o = 16; o; o >>= 1) s += __shfl_xor_sync(0xFFFFFFFFu, s, o);
    if (lane == 0) bp.out[l][n] = bp.bhh[l][n] + bp.bxh[l][n] + s;
}

// hi/lo interleaved splits
__global__ void k_split_x(const float* __restrict__ x, bf16* __restrict__ dst)
{
    const size_t idx = (size_t)blockIdx.x * blockDim.x + threadIdx.x;
    const size_t row = idx >> 4;
    const int    kc  = (int)(idx & 15);
    const float* src = x + row * 512 + kc * 32;
    bf16* d = dst + row * RSTRIDE + kc * 64;

    uint32_t hi[16], lo[16];
#pragma unroll
    for (int j = 0; j < 8; ++j) {
        float4 v = *(const float4*)(src + j * 4);
        __nv_bfloat162 h0, l0, h1, l1;
        split2(v.x, h0.x, l0.x); split2(v.y, h0.y, l0.y);
        split2(v.z, h1.x, l1.x); split2(v.w, h1.y, l1.y);
        hi[2*j]   = *(uint32_t*)&h0; hi[2*j+1] = *(uint32_t*)&h1;
        lo[2*j]   = *(uint32_t*)&l0; lo[2*j+1] = *(uint32_t*)&l1;
    }
#pragma unroll
    for (int j = 0; j < 4; ++j) {
        ((uint4*)d)[j]      = *(uint4*)(hi + 4*j);
        ((uint4*)(d+32))[j] = *(uint4*)(lo + 4*j);
    }
}

struct WPtrs { const float* p[2]; };

__global__ void k_split_w(WPtrs wp, bf16* __restrict__ dst)
{
    const size_t idx = (size_t)blockIdx.x * blockDim.x + threadIdx.x;
    const int slot = (int)(idx >> 13);             // 0 or 1
    const size_t row = (idx >> 4) & 511;
    const int    kc  = (int)(idx & 15);
    const float* src = wp.p[slot] + row * 512 + kc * 32;
    // slot 0 -> Whl slot 0 (W_xh0), slot 1 -> Whl slot 3 (final projection)
    bf16* d = dst + (size_t)(slot * 3) * WELEMS + row * RSTRIDE + kc * 64;

    uint32_t hi[16], lo[16];
#pragma unroll
    for (int j = 0; j < 8; ++j) {
        float4 v = *(const float4*)(src + j * 4);
        __nv_bfloat162 h0, l0, h1, l1;
        split2(v.x, h0.x, l0.x); split2(v.y, h0.y, l0.y);
        split2(v.z, h1.x, l1.x); split2(v.w, h1.y, l1.y);
        hi[2*j]   = *(uint32_t*)&h0; hi[2*j+1] = *(uint32_t*)&h1;
        lo[2*j]   = *(uint32_t*)&l0; lo[2*j+1] = *(uint32_t*)&l1;
    }
#pragma unroll
    for (int j = 0; j < 4; ++j) {
        ((uint4*)d)[j]      = *(uint4*)(hi + 4*j);
        ((uint4*)(d+32))[j] = *(uint4*)(lo + 4*j);
    }
}

// --------------------------------- launcher ---------------------------------
extern "C" void kernel_launch(void* const* d_in, const int* in_sizes, int n_in,
                              void* d_out, int out_size)
{
    const float* xs     = (const float*)d_in[0];
    const float* W_xh0  = (const float*)d_in[1];
    const float* b_xh0  = (const float*)d_in[2];
    const float* b_hh0  = (const float*)d_in[4];
    const float* W_hy0  = (const float*)d_in[5];
    const float* b_hy0  = (const float*)d_in[6];
    const float* W_xh_h = (const float*)d_in[7];
    const float* b_xh_h = (const float*)d_in[8];
    const float* W_hh_h = (const float*)d_in[9];
    const float* b_hh_h = (const float*)d_in[10];
    const float* W_hy_h = (const float*)d_in[11];
    const float* b_hy_h = (const float*)d_in[12];

    float* out = (float*)d_out;
    float* hs_final = out + (size_t)4096 * 8 * HD;

    bf16 *Xhl, *H0hl, *H1hl, *Whl;
    float *beff;
    cudaGetSymbolAddress((void**)&Xhl,  g_Xhl);
    cudaGetSymbolAddress((void**)&H0hl, g_H0hl);
    cudaGetSymbolAddress((void**)&H1hl, g_H1hl);
    cudaGetSymbolAddress((void**)&Whl,  g_Whl);
    cudaGetSymbolAddress((void**)&beff, g_beff);

    cudaFuncSetAttribute(gemm_stage<true,  false, false>,
                         cudaFuncAttributeMaxDynamicSharedMemorySize, SMEMB);
    cudaFuncSetAttribute(gemm_stage<true,  true,  false>,
                         cudaFuncAttributeMaxDynamicSharedMemorySize, SMEMB);
    cudaFuncSetAttribute(gemm_stage<false, false, true >,
                         cudaFuncAttributeMaxDynamicSharedMemorySize, SMEMB);

#define WS(s) (Whl + (size_t)(s) * WELEMS)

    // ---- prep: fused effective weights (direct interleaved output) ----
    WeffP wep;
    wep.A[0] = W_xh_h;        wep.A[1] = W_xh_h + WSZ;
    wep.B[0] = W_hy0;         wep.B[1] = W_hy_h;
    wep.Wadd[0] = W_hh_h;     wep.Wadd[1] = W_hh_h + WSZ;
    wep.C[0] = WS(1);         wep.C[1] = WS(2);
    k_weff<<<dim3(8, 8, 2), 256>>>(wep);

    BeffP bep;
    bep.Wxh[0] = W_xh_h;      bep.Wxh[1] = W_xh_h + WSZ;
    bep.bhh[0] = b_hh_h;      bep.bhh[1] = b_hh_h + HD;
    bep.bxh[0] = b_xh_h;      bep.bxh[1] = b_xh_h + HD;
    bep.bhy[0] = b_hy0;       bep.bhy[1] = b_hy_h;
    bep.out[0] = beff;        bep.out[1] = beff + HD;
    k_beff<<<128, 256>>>(bep);

    // ---- prep: hi/lo interleaved splits ----
    k_split_x<<<2048, 256>>>(xs, Xhl);
    WPtrs wp;
    wp.p[0] = W_xh0;
    wp.p[1] = W_hy_h + WSZ;
    k_split_w<<<64, 256>>>(wp, Whl);

    dim3 grid(HD / BN, MROWS / BM);   // (4, 256) = 1024 CTAs
    dim3 block(NTH);

    // 1) h0 = tanh(X @ W_xh0^T + b_xh0 + b_hh0)
    gemm_stage<true, false, false><<<grid, block, SMEMB>>>(
        Xhl, WS(0), b_xh0, b_hh0, H0hl, nullptr, nullptr);
    // 2) h1 = tanh(h0 @ Weff0^T + beff0)
    gemm_stage<true, false, false><<<grid, block, SMEMB>>>(
        H0hl, WS(1), beff, nullptr, H1hl, nullptr, nullptr);
    // 3) h2 = tanh(h1 @ Weff1^T + beff1)  (+ hs_final)
    gemm_stage<true, true, false><<<grid, block, SMEMB>>>(
        H1hl, WS(2), beff + HD, nullptr, H0hl, nullptr, hs_final);
    // 4) outputs = (h2 @ W_hy_h[1]^T + b_hy_h[1]) -> [S, B, H] fp32
    gemm_stage<false, false, true><<<grid, block, SMEMB>>>(
        H0hl, WS(3), b_hy_h + HD, nullptr, nullptr, out, nullptr);
#undef WS
}